// round 5
// baseline (speedup 1.0000x reference)
#include <cuda_runtime.h>

#define IMG 224
#define NPIX (IMG * IMG)        // 50176
#define NUM_VIEWS 6
#define NBATCH 16
#define NPTS 32768
#define THREADS 1024

// Anchor image: anchors range [-2,223]+2 -> rows/cols 0..225, rows padded to
// 228 floats (912B, 16B-aligned).
#define AH 226
#define AW 228
#define ASZ (AH * AW)           // 51528 floats = 206112 bytes
#define LISTCAP 3000

// dynamic smem layout (bytes):
//   [0, 206112)        float A[AH][AW]
//   [206112, 230112)   uint2 list[LISTCAP]
//   [230112, 230240)   float red_min[32]
//   [230240, 230368)   float red_max[32]
//   [230368, 230372)   int cnt
#define OFF_LIST 206112
#define OFF_RMIN 230112
#define OFF_RMAX 230240
#define OFF_CNT  230368
#define SMEM_BYTES 230400

__global__ __launch_bounds__(THREADS, 1)
void render_kernel(const float* __restrict__ points, float* __restrict__ out) {
    extern __shared__ char smem[];
    float* A       = (float*)smem;
    uint2* rlist   = (uint2*)(smem + OFF_LIST);
    float* red_min = (float*)(smem + OFF_RMIN);
    float* red_max = (float*)(smem + OFF_RMAX);
    int*   cntp    = (int*)  (smem + OFF_CNT);

    const int bv  = blockIdx.x;
    const int b   = bv / NUM_VIEWS;
    const int v   = bv % NUM_VIEWS;
    const int tid = threadIdx.x;
    const int wid = tid >> 5, lid = tid & 31;

    const float deg2rad = 0.017453292519943295f;
    const float a = (float)(v * 60) * deg2rad;
    const float el_tab[NUM_VIEWS] = {0.f, 30.f, -30.f, 0.f, 0.f, 0.f};
    const float e = el_tab[v] * deg2rad;
    const float ca = cosf(a), sa = sinf(a), ce = cosf(e), se = sinf(e);

    const float4* __restrict__ pb4 =
        (const float4*)(points + (size_t)b * NPTS * 3);

    if (tid == 0) *cntp = 0;

    // ---- Pass 1: zmin/zmax of z_fin (float4 loads: 4 pts / 3 LDG.128) ----
    float zmn = INFINITY, zmx = -INFINITY;
    for (int g = tid; g < NPTS / 4; g += THREADS) {
        float4 p0 = pb4[3 * g + 0];
        float4 p1 = pb4[3 * g + 1];
        float4 p2 = pb4[3 * g + 2];
        float xs[4] = {p0.x, p0.w, p1.z, p2.y};
        float ys[4] = {p0.y, p1.x, p1.w, p2.z};
        float zs[4] = {p0.z, p1.y, p2.x, p2.w};
        #pragma unroll
        for (int k = 0; k < 4; k++) {
            float zr = xs[k] * sa + zs[k] * ca;
            float zf = ys[k] * se + zr * ce;
            zmn = fminf(zmn, zf);
            zmx = fmaxf(zmx, zf);
        }
    }
    #pragma unroll
    for (int o = 16; o > 0; o >>= 1) {
        zmn = fminf(zmn, __shfl_xor_sync(0xffffffffu, zmn, o));
        zmx = fmaxf(zmx, __shfl_xor_sync(0xffffffffu, zmx, o));
    }
    if (lid == 0) { red_min[wid] = zmn; red_max[wid] = zmx; }

    // zero anchor image while the reduction settles
    {
        float4 zv = make_float4(0.f, 0.f, 0.f, 0.f);
        float4* A4 = (float4*)A;
        for (int i = tid; i < ASZ / 4; i += THREADS) A4[i] = zv;
    }
    __syncthreads();

    if (wid == 0) {
        zmn = red_min[lid];
        zmx = red_max[lid];
        #pragma unroll
        for (int o = 16; o > 0; o >>= 1) {
            zmn = fminf(zmn, __shfl_xor_sync(0xffffffffu, zmn, o));
            zmx = fmaxf(zmx, __shfl_xor_sync(0xffffffffu, zmx, o));
        }
        if (lid == 0) { red_min[0] = zmn; red_max[0] = zmx; }
    }
    __syncthreads();
    zmn = red_min[0];
    const float scale = 0.7f / (red_max[0] - zmn + 1e-6f);   // hoisted reciprocal

    // ---- Pass 2: rotate + single-anchor write (fast) / warp-agg list (rare) ----
    const float off0 = -2.0f / 224.0f;
    const float off4 =  2.0f / 224.0f;
    int* iA = (int*)A;

    for (int g = tid; g < NPTS / 4; g += THREADS) {
        float4 p0 = pb4[3 * g + 0];
        float4 p1 = pb4[3 * g + 1];
        float4 p2 = pb4[3 * g + 2];
        float xs[4] = {p0.x, p0.w, p1.z, p2.y};
        float ys[4] = {p0.y, p1.x, p1.w, p2.z};
        float zs[4] = {p0.z, p1.y, p2.x, p2.w};
        #pragma unroll
        for (int k = 0; k < 4; k++) {
            float x = xs[k], y = ys[k], z = zs[k];
            float xr = x * ca - z * sa;
            float zr = x * sa + z * ca;
            float yr = y * ce - zr * se;
            float zf = y * se + zr * ce;

            // identical fp expressions to the validated R3 path
            int px0 = (int)((xr + off0 + 1.0f) * 0.5f * (float)(IMG - 1));
            int px4 = (int)((xr + off4 + 1.0f) * 0.5f * (float)(IMG - 1));
            int py0 = (int)((yr + off0 + 1.0f) * 0.5f * (float)(IMG - 1));
            int py4 = (int)((yr + off4 + 1.0f) * 0.5f * (float)(IMG - 1));

            int xlo = max(px0, 0), xhi = min(px4, IMG - 1);
            int ylo = max(py0, 0), yhi = min(py4, IMG - 1);

            float feat = 0.3f + (zf - zmn) * scale;
            int fb = __float_as_int(feat);          // positive floats order as ints

            bool valid = (xlo <= xhi) && (ylo <= yhi);
            bool fast  = valid && ((px4 - px0) == 2) && ((py4 - py0) == 2);
            bool rare  = valid && !fast;

            if (fast) {
                // exact 3x3 rect anchored at (px0,py0): one anchor atomic;
                // boundary clipping handled by the dilation output window
                atomicMax(&iA[(py0 + 2) * AW + (px0 + 2)], fb);
            }
            unsigned rmask = __ballot_sync(0xffffffffu, rare);
            if (rare) {
                int leader = __ffs(rmask) - 1;
                int prefix = __popc(rmask & ((1u << lid) - 1u));
                int base = 0;
                if (lid == leader) base = atomicAdd(cntp, __popc(rmask));
                base = __shfl_sync(rmask, base, leader);
                int idx = base + prefix;
                if (idx < LISTCAP) {
                    uint2 ent;
                    ent.x = (unsigned)xlo | ((unsigned)xhi << 8) |
                            ((unsigned)ylo << 16) | ((unsigned)yhi << 24);
                    ent.y = (unsigned)fb;
                    rlist[idx] = ent;
                }
            }
        }
    }
    __syncthreads();
    const int rare_cnt = min(*cntp, LISTCAP);

    // ---- H-pass: in-place row-wise max3, A[j][x] <- max(A[j][x..x+2]) ----
    const int r = tid >> 2;        // row 0..255 (valid < 226)
    const int q = tid & 3;         // quarter: 56 outputs each
    float* rowp = A + r * AW + q * 56;
    float ov0 = 0.f, ov1 = 0.f;
    if (r < AH) { ov0 = rowp[56]; ov1 = rowp[57]; }   // overlap preload
    __syncthreads();
    if (r < AH) {
        float4* rp = (float4*)rowp;
        float4 cur = rp[0];
        #pragma unroll
        for (int gg = 0; gg < 14; gg++) {
            float4 nxt;
            if (gg < 13) nxt = rp[gg + 1];
            else { nxt.x = ov0; nxt.y = ov1; nxt.z = 0.f; nxt.w = 0.f; }
            float4 o;
            o.x = fmaxf(cur.x, fmaxf(cur.y, cur.z));
            o.y = fmaxf(cur.y, fmaxf(cur.z, cur.w));
            o.z = fmaxf(cur.z, fmaxf(cur.w, nxt.x));
            o.w = fmaxf(cur.w, fmaxf(nxt.x, nxt.y));
            rp[gg] = o;
            cur = nxt;
        }
    }
    __syncthreads();

    // ---- V-pass fused with 3-channel epilogue (no integer division) ----
    float* __restrict__ ob = out + (size_t)bv * 3 * NPIX;
    float4* __restrict__ ob4 = (float4*)ob;
    {
        int y  = tid / 56;          // one constant-div (mul/shift), then incremental
        int xq = tid - y * 56;
        for (int i = tid; i < NPIX / 4; i += THREADS) {
            const float* base = A + y * AW + 4 * xq;
            const float4 va = *(const float4*)(base);
            const float4 vb = *(const float4*)(base + AW);
            const float4 vc = *(const float4*)(base + 2 * AW);
            float4 o;
            o.x = fmaxf(va.x, fmaxf(vb.x, vc.x));
            o.y = fmaxf(va.y, fmaxf(vb.y, vc.y));
            o.z = fmaxf(va.z, fmaxf(vb.z, vc.z));
            o.w = fmaxf(va.w, fmaxf(vb.w, vc.w));
            ob4[i]                = o;
            ob4[i + NPIX / 4]     = o;
            ob4[i + 2 * NPIX / 4] = o;
            // advance (i += 1024) -> (y += 18, xq += 16) with wrap
            y += 18; xq += 16;
            if (xq >= 56) { xq -= 56; y += 1; }
        }
    }
    __threadfence_block();
    __syncthreads();

    // ---- Rare points: exact direct global atomics on all 3 channels ----
    int* iob = (int*)ob;
    for (int i = tid; i < rare_cnt; i += THREADS) {
        uint2 ent = rlist[i];
        int xlo = ent.x & 255, xhi = (ent.x >> 8) & 255;
        int ylo = (ent.x >> 16) & 255, yhi = (ent.x >> 24) & 255;
        int fb = (int)ent.y;
        for (int yy = ylo; yy <= yhi; yy++) {
            int rowbase = yy * IMG;
            for (int xx = xlo; xx <= xhi; xx++) {
                int* p = iob + rowbase + xx;
                atomicMax(p, fb);
                atomicMax(p + NPIX, fb);
                atomicMax(p + 2 * NPIX, fb);
            }
        }
    }
}

extern "C" void kernel_launch(void* const* d_in, const int* in_sizes, int n_in,
                              void* d_out, int out_size) {
    const float* points = (const float*)d_in[0];
    float* out = (float*)d_out;

    cudaFuncSetAttribute(render_kernel,
                         cudaFuncAttributeMaxDynamicSharedMemorySize, SMEM_BYTES);
    render_kernel<<<NBATCH * NUM_VIEWS, THREADS, SMEM_BYTES>>>(points, out);
}

// round 6
// speedup vs baseline: 1.5005x; 1.5005x over previous
#include <cuda_runtime.h>

#define IMG 224
#define NPIX (IMG * IMG)        // 50176
#define NUM_VIEWS 6
#define NBATCH 16
#define NPTS 32768
#define THREADS 1024
#define NGROUPS (NPTS / 4)      // 8192 float4-groups of 4 points
#define NITERS (NGROUPS / THREADS)  // 8 iterations, exact

__global__ __launch_bounds__(THREADS, 1)
void render_kernel(const float* __restrict__ points, float* __restrict__ out) {
    extern __shared__ float simg[];          // NPIX floats (image accumulator)
    __shared__ float red_min[32], red_max[32];

    const int bv  = blockIdx.x;
    const int b   = bv / NUM_VIEWS;
    const int v   = bv % NUM_VIEWS;
    const int tid = threadIdx.x;
    const int wid = tid >> 5, lid = tid & 31;

    const float deg2rad = 0.017453292519943295f;
    const float a = (float)(v * 60) * deg2rad;
    const float el_tab[NUM_VIEWS] = {0.f, 30.f, -30.f, 0.f, 0.f, 0.f};
    const float e = el_tab[v] * deg2rad;
    const float ca = cosf(a), sa = sinf(a), ce = cosf(e), se = sinf(e);
    // fused z_fin coefficients (pass 1 only; perturbs zmin/zmax by ulps)
    const float kx = sa * ce, ky = se, kz = ca * ce;

    const float4* __restrict__ pb4 =
        (const float4*)(points + (size_t)b * NPTS * 3);

    // ---- Pass 1: zmin/zmax of z_fin, double-buffered loads ----
    float zmn = INFINITY, zmx = -INFINITY;
    {
        float4 c0 = pb4[3 * tid + 0];
        float4 c1 = pb4[3 * tid + 1];
        float4 c2 = pb4[3 * tid + 2];
        #pragma unroll 1
        for (int it = 0; it < NITERS; it++) {
            float4 n0, n1, n2;
            if (it < NITERS - 1) {
                int gn = 3 * (tid + (it + 1) * THREADS);
                n0 = pb4[gn + 0];
                n1 = pb4[gn + 1];
                n2 = pb4[gn + 2];
            }
            float xs[4] = {c0.x, c0.w, c1.z, c2.y};
            float ys[4] = {c0.y, c1.x, c1.w, c2.z};
            float zs[4] = {c0.z, c1.y, c2.x, c2.w};
            #pragma unroll
            for (int k = 0; k < 4; k++) {
                float zf = xs[k] * kx + ys[k] * ky + zs[k] * kz;
                zmn = fminf(zmn, zf);
                zmx = fmaxf(zmx, zf);
            }
            c0 = n0; c1 = n1; c2 = n2;
        }
    }
    #pragma unroll
    for (int o = 16; o > 0; o >>= 1) {
        zmn = fminf(zmn, __shfl_xor_sync(0xffffffffu, zmn, o));
        zmx = fmaxf(zmx, __shfl_xor_sync(0xffffffffu, zmx, o));
    }
    if (lid == 0) { red_min[wid] = zmn; red_max[wid] = zmx; }

    // zero the shared image while the reduction settles
    {
        float4 zv = make_float4(0.f, 0.f, 0.f, 0.f);
        float4* s4 = (float4*)simg;
        for (int i = tid; i < NPIX / 4; i += THREADS) s4[i] = zv;
    }
    __syncthreads();

    if (wid == 0) {
        zmn = red_min[lid];
        zmx = red_max[lid];
        #pragma unroll
        for (int o = 16; o > 0; o >>= 1) {
            zmn = fminf(zmn, __shfl_xor_sync(0xffffffffu, zmn, o));
            zmx = fmaxf(zmx, __shfl_xor_sync(0xffffffffu, zmx, o));
        }
        if (lid == 0) { red_min[0] = zmn; red_max[0] = zmx; }
    }
    __syncthreads();
    zmn = red_min[0];
    const float scale = 0.7f / (red_max[0] - zmn + 1e-6f);   // hoisted reciprocal

    // ---- Pass 2: rotate + branch-free 3x3 splat, double-buffered loads ----
    const float off0 = -2.0f / 224.0f;
    const float off4 =  2.0f / 224.0f;
    int* iimg = (int*)simg;

    {
        float4 c0 = pb4[3 * tid + 0];
        float4 c1 = pb4[3 * tid + 1];
        float4 c2 = pb4[3 * tid + 2];
        #pragma unroll 1
        for (int it = 0; it < NITERS; it++) {
            float4 n0, n1, n2;
            if (it < NITERS - 1) {
                int gn = 3 * (tid + (it + 1) * THREADS);
                n0 = pb4[gn + 0];
                n1 = pb4[gn + 1];
                n2 = pb4[gn + 2];
            }
            float xs[4] = {c0.x, c0.w, c1.z, c2.y};
            float ys[4] = {c0.y, c1.x, c1.w, c2.z};
            float zs[4] = {c0.z, c1.y, c2.x, c2.w};
            #pragma unroll
            for (int k = 0; k < 4; k++) {
                float x = xs[k], y = ys[k], z = zs[k];
                float xr = x * ca - z * sa;
                float zr = x * sa + z * ca;
                float yr = y * ce - zr * se;
                float zf = y * se + zr * ce;

                // identical fp expressions to the reference path (bit-exact
                // pixel coverage)
                int px0 = (int)((xr + off0 + 1.0f) * 0.5f * (float)(IMG - 1));
                int px4 = (int)((xr + off4 + 1.0f) * 0.5f * (float)(IMG - 1));
                int py0 = (int)((yr + off0 + 1.0f) * 0.5f * (float)(IMG - 1));
                int py4 = (int)((yr + off4 + 1.0f) * 0.5f * (float)(IMG - 1));

                int xlo = max(px0, 0), xhi = min(px4, IMG - 1);
                int ylo = max(py0, 0), yhi = min(py4, IMG - 1);
                if (xlo > xhi || ylo > yhi) continue;

                float feat = 0.3f + (zf - zmn) * scale;   // in [0.3, 1.0]
                int fb = __float_as_int(feat);            // positive floats order as ints

                // rect extent <= 3 per axis; min-clamp collapses the unrolled
                // 3x3 onto the exact valid rect (duplicates idempotent under max)
                int x1 = min(xlo + 1, xhi);
                int y1 = min(ylo + 1, yhi);
                int rA = ylo * IMG, rB = y1 * IMG, rC = yhi * IMG;
                atomicMax(&iimg[rA + xlo], fb);
                atomicMax(&iimg[rA + x1 ], fb);
                atomicMax(&iimg[rA + xhi], fb);
                atomicMax(&iimg[rB + xlo], fb);
                atomicMax(&iimg[rB + x1 ], fb);
                atomicMax(&iimg[rB + xhi], fb);
                atomicMax(&iimg[rC + xlo], fb);
                atomicMax(&iimg[rC + x1 ], fb);
                atomicMax(&iimg[rC + xhi], fb);
            }
            c0 = n0; c1 = n1; c2 = n2;
        }
    }
    __syncthreads();

    // ---- Epilogue: broadcast image to 3 channels of out[b][v][c][h][w] ----
    float* __restrict__ ob = out + (size_t)bv * 3 * NPIX;
    float4* __restrict__ ob4 = (float4*)ob;
    const float4* __restrict__ s4 = (const float4*)simg;
    for (int i = tid; i < NPIX / 4; i += THREADS) {
        float4 val = s4[i];
        ob4[i]                = val;
        ob4[i + NPIX / 4]     = val;
        ob4[i + 2 * NPIX / 4] = val;
    }
}

extern "C" void kernel_launch(void* const* d_in, const int* in_sizes, int n_in,
                              void* d_out, int out_size) {
    const float* points = (const float*)d_in[0];
    float* out = (float*)d_out;

    const size_t smem = (size_t)NPIX * sizeof(float);  // 200704 bytes
    cudaFuncSetAttribute(render_kernel,
                         cudaFuncAttributeMaxDynamicSharedMemorySize, (int)smem);

    render_kernel<<<NBATCH * NUM_VIEWS, THREADS, smem>>>(points, out);
}